// round 3
// baseline (speedup 1.0000x reference)
#include <cuda_runtime.h>
#include <cstdint>

// ---------------- problem constants ----------------
#define NE   8
#define NT   16384
#define NIN  2048
#define NOUT 2048

// ---------------- GEMM tiling ----------------
#define BM 128
#define BN 256
#define BK 32
#define KITERS (NIN / BK)            // 64
#define STAGES 3
#define A_STAGE_BYTES (BM * BK * 4)  // 16384
#define B_STAGE_BYTES (BN * BK * 4)  // 32768
#define STAGE_BYTES (A_STAGE_BYTES + B_STAGE_BYTES)   // 49152
#define SMEM_TOTAL (STAGES * STAGE_BYTES)             // 147456

// ---------------- scratch: tf32-rounded, fragment-native layouts ----------------
// g_A: [b(128)][kc(256)][mtile(8)][t(32)*4 + j]   (4 KB per (b,kc))
// g_W: [nb(64)][kc(256)][ntile(32)][t(32)*2 + j]  (8 KB per (nb,kc))
__device__ float g_A[(size_t)NT * NIN];
__device__ float g_W[(size_t)NE * NOUT * NIN];

// ---------------- helpers (all plain-sm_103-legal: sm_80 era) ----------------
__device__ __forceinline__ uint32_t smem_u32(const void* p) {
    uint32_t a;
    asm("{ .reg .u64 t; cvta.to.shared.u64 t, %1; cvt.u32.u64 %0, t; }" : "=r"(a) : "l"(p));
    return a;
}

__device__ __forceinline__ float tf32r(float f) {   // round-to-nearest tf32 (unbiased)
    uint32_t r;
    asm("cvt.rna.tf32.f32 %0, %1;" : "=r"(r) : "f"(f));
    return __uint_as_float(r);
}

__device__ __forceinline__ void cp16(uint32_t smem_dst, const float* gsrc) {
    asm volatile("cp.async.cg.shared.global [%0], [%1], 16;" :: "r"(smem_dst), "l"(gsrc));
}
#define CP_COMMIT() asm volatile("cp.async.commit_group;" ::: "memory")
#define CP_WAIT1()  asm volatile("cp.async.wait_group 1;" ::: "memory")

__device__ __forceinline__ void lds128(uint32_t* r, uint32_t addr) {
    asm volatile("ld.shared.v4.b32 {%0,%1,%2,%3}, [%4];"
                 : "=r"(r[0]), "=r"(r[1]), "=r"(r[2]), "=r"(r[3]) : "r"(addr));
}
__device__ __forceinline__ void lds64(uint32_t* r, uint32_t addr) {
    asm volatile("ld.shared.v2.b32 {%0,%1}, [%2];"
                 : "=r"(r[0]), "=r"(r[1]) : "r"(addr));
}

__device__ __forceinline__ void mma_tf32(float* d, const uint32_t* a, const uint32_t* b) {
    asm volatile(
        "mma.sync.aligned.m16n8k8.row.col.f32.tf32.tf32.f32 "
        "{%0,%1,%2,%3}, {%4,%5,%6,%7}, {%8,%9}, {%0,%1,%2,%3};"
        : "+f"(d[0]), "+f"(d[1]), "+f"(d[2]), "+f"(d[3])
        : "r"(a[0]), "r"(a[1]), "r"(a[2]), "r"(a[3]), "r"(b[0]), "r"(b[1]));
}

// ---------------- pre-pass A: x[row][col] -> g_A fragment-native, tf32-rounded ----
// one thread produces 16 contiguous output floats (64B) from 2 rows x 8 cols.
__global__ void __launch_bounds__(256) prepA(const float* __restrict__ x) {
    uint32_t gid = blockIdx.x * 256 + threadIdx.x;     // [0, 2^21)
    int lrg   = gid & 7;
    int mtile = (gid >> 3) & 7;
    int kc    = (gid >> 6) & 255;
    int b     = gid >> 14;
    int row0  = b * 128 + mtile * 16 + lrg;            // lr in [0,8)
    int c     = kc * 8;

    const float* r0 = x + (size_t)row0 * NIN + c;
    const float* r1 = r0 + (size_t)8 * NIN;            // lr+8
    float4 u0 = *(const float4*)(r0);                  // row0 cols c..c+3
    float4 u1 = *(const float4*)(r0 + 4);              // row0 cols c+4..c+7
    float4 v0 = *(const float4*)(r1);
    float4 v1 = *(const float4*)(r1 + 4);

    float* dst = g_A + ((((size_t)b * 256 + kc) * 8 + mtile) * 128) + lrg * 16;
    // t = lrg*4 + i ; regs [j0,j1,j2,j3] = [(lr,c+i),(lr+8,c+i),(lr,c+4+i),(lr+8,c+4+i)]
    float4 o;
    o.x = tf32r(u0.x); o.y = tf32r(v0.x); o.z = tf32r(u1.x); o.w = tf32r(v1.x);
    *(float4*)(dst + 0)  = o;
    o.x = tf32r(u0.y); o.y = tf32r(v0.y); o.z = tf32r(u1.y); o.w = tf32r(v1.y);
    *(float4*)(dst + 4)  = o;
    o.x = tf32r(u0.z); o.y = tf32r(v0.z); o.z = tf32r(u1.z); o.w = tf32r(v1.z);
    *(float4*)(dst + 8)  = o;
    o.x = tf32r(u0.w); o.y = tf32r(v0.w); o.z = tf32r(u1.w); o.w = tf32r(v1.w);
    *(float4*)(dst + 12) = o;
}

// ---------------- pre-pass W: w[grow][col] -> g_W fragment-native ----------------
// one thread produces 8 contiguous output floats (32B) from 1 row x 8 cols.
__global__ void __launch_bounds__(256) prepW(const float* __restrict__ w) {
    uint32_t gid = blockIdx.x * 256 + threadIdx.x;     // [0, 2^22)
    int ln    = gid & 7;
    int ntile = (gid >> 3) & 31;
    int kc    = (gid >> 8) & 255;
    int nb    = gid >> 16;
    int grow  = nb * 256 + ntile * 8 + ln;
    int c     = kc * 8;

    const float* r = w + (size_t)grow * NIN + c;
    float4 v0 = *(const float4*)(r);        // cols c..c+3   (lk 0..3 -> j=0)
    float4 v1 = *(const float4*)(r + 4);    // cols c+4..c+7 (lk 4..7 -> j=1)

    float* dst = g_W + ((((size_t)nb * 256 + kc) * 32 + ntile) * 64) + ln * 8;
    float4 o;
    o.x = tf32r(v0.x); o.y = tf32r(v1.x); o.z = tf32r(v0.y); o.w = tf32r(v1.y);
    *(float4*)(dst + 0) = o;
    o.x = tf32r(v0.z); o.y = tf32r(v1.z); o.z = tf32r(v0.w); o.w = tf32r(v1.w);
    *(float4*)(dst + 4) = o;
}

// ---------------- main grouped GEMM (sm80-style pipelined mma.sync) -------------
__global__ void __launch_bounds__(256, 1) gemm_kernel(
        const float* __restrict__ bias,
        const int*   __restrict__ tpe,
        float*       __restrict__ out) {
    extern __shared__ __align__(16) char smem[];

    const int e  = blockIdx.z;
    const int mt = blockIdx.y;
    const int nt = blockIdx.x;

    int start = 0, mycnt = 0;
    #pragma unroll
    for (int i = 0; i < NE; i++) {
        int cc = __ldg(tpe + i);
        if (i < e) start += cc;
        if (i == e) mycnt = cc;
    }
    if (mt * BM >= mycnt) return;

    const int tid  = threadIdx.x;
    const int lane = tid & 31;
    const int wid  = tid >> 5;
    const int wm   = wid & 1;        // 2 warp rows (64 rows each)
    const int wn   = wid >> 1;       // 4 warp cols (64 cols each)

    const int b  = (start >> 7) + mt;      // A 128-row block index
    const int nb = e * 8 + nt;             // W 256-row block index
    const int m0 = start + mt * BM;

    const uint32_t sb = smem_u32(smem);
    const float* Ab = g_A + (size_t)b  * 256 * 1024;   // [kc][1024 floats]
    const float* Bb = g_W + (size_t)nb * 256 * 2048;   // [kc][2048 floats]

    // ---- stage issue: 12 x cp.async(16B) per thread ----
    auto issue = [&](int it, int s) {
        const float* As = Ab + (size_t)it * 4 * 1024;
        const float* Bs = Bb + (size_t)it * 4 * 2048;
        uint32_t dA = sb + s * STAGE_BYTES;
        uint32_t dB = dA + A_STAGE_BYTES;
        #pragma unroll
        for (int kcl = 0; kcl < 4; kcl++) {
            cp16(dA + kcl * 4096 + tid * 16,        As + kcl * 1024 + tid * 4);
            cp16(dB + kcl * 8192 + tid * 16,        Bs + kcl * 2048 + tid * 4);
            cp16(dB + kcl * 8192 + 4096 + tid * 16, Bs + kcl * 2048 + 1024 + tid * 4);
        }
        CP_COMMIT();
    };

    issue(0, 0);
    issue(1, 1);

    float acc[4][8][4];
    #pragma unroll
    for (int i = 0; i < 4; i++)
        #pragma unroll
        for (int j = 0; j < 8; j++)
            #pragma unroll
            for (int k = 0; k < 4; k++) acc[i][j][k] = 0.0f;

    #pragma unroll 1
    for (int it = 0; it < KITERS; ++it) {
        const int s = it % STAGES;
        CP_WAIT1();
        __syncthreads();
        if (it + 2 < KITERS) issue(it + 2, (it + 2) % STAGES);
        else CP_COMMIT();                       // keep group count uniform

        const uint32_t aBase = sb + s * STAGE_BYTES;
        const uint32_t bBase = aBase + A_STAGE_BYTES;
        #pragma unroll
        for (int kcl = 0; kcl < 4; kcl++) {
            uint32_t af[4][4], bf[8][2];
            #pragma unroll
            for (int i = 0; i < 4; i++)
                lds128(af[i], aBase + ((kcl * 8 + wm * 4 + i) * 128 + lane * 4) * 4);
            #pragma unroll
            for (int j = 0; j < 8; j++)
                lds64(bf[j], bBase + ((kcl * 32 + wn * 8 + j) * 64 + lane * 2) * 4);
            #pragma unroll
            for (int i = 0; i < 4; i++)
                #pragma unroll
                for (int j = 0; j < 8; j++)
                    mma_tf32(acc[i][j], af[i], bf[j]);
        }
    }

    // ---- epilogue: bias add + fp32 store ----
    const int ncol0 = nt * BN + wn * 64;                 // global out col base
    const float* bptr = bias + (size_t)e * NOUT + ncol0;
    #pragma unroll
    for (int j = 0; j < 8; j++) {
        const int cb = j * 8 + (lane & 3) * 2;
        const float bx = __ldg(bptr + cb);
        const float by = __ldg(bptr + cb + 1);
        #pragma unroll
        for (int i = 0; i < 4; i++) {
            const int r0 = wm * 64 + i * 16 + (lane >> 2);
            if (mt * BM + r0 < mycnt) {
                float2 v = make_float2(acc[i][j][0] + bx, acc[i][j][1] + by);
                *(float2*)(out + (size_t)(m0 + r0) * NOUT + ncol0 + cb) = v;
            }
            if (mt * BM + r0 + 8 < mycnt) {
                float2 v = make_float2(acc[i][j][2] + bx, acc[i][j][3] + by);
                *(float2*)(out + (size_t)(m0 + r0 + 8) * NOUT + ncol0 + cb) = v;
            }
        }
    }
}

// ---------------- host launch ----------------
extern "C" void kernel_launch(void* const* d_in, const int* in_sizes, int n_in,
                              void* d_out, int out_size) {
    const float* x    = (const float*)d_in[0];
    const float* w    = (const float*)d_in[1];
    const float* bias = (const float*)d_in[2];
    const int*   tpe  = (const int*)d_in[3];
    float*       out  = (float*)d_out;

    // prepA needs NT*NIN/16 = 2^21 threads -> 8192 blocks of 256 (R2 bug: was 2048)
    prepA<<<(NT / 16) * (NIN / 256) / 16 * 16, 256>>>(x);  // 8192 blocks
    prepW<<<16384, 256>>>(w);                              // 2^22 threads

    cudaFuncSetAttribute(gemm_kernel,
                         cudaFuncAttributeMaxDynamicSharedMemorySize, SMEM_TOTAL);
    dim3 grid(NOUT / BN, NT / BM, NE);                     // (8, 128, 8), ragged exit
    gemm_kernel<<<grid, 256, SMEM_TOTAL>>>(bias, tpe, out);
}

// round 4
// speedup vs baseline: 1.1784x; 1.1784x over previous
#include <cuda_runtime.h>
#include <cstdint>

// ---------------- problem constants ----------------
#define NE   8
#define NT   16384
#define NIN  2048
#define NOUT 2048

// ---------------- GEMM tiling ----------------
#define BM 128
#define BN 256
#define BK 32
#define KITERS (NIN / BK)            // 64
#define STAGES 4
#define A_STAGE_BYTES (BM * BK * 4)  // 16384
#define B_STAGE_BYTES (BN * BK * 4)  // 32768
#define STAGE_BYTES (A_STAGE_BYTES + B_STAGE_BYTES)   // 49152
#define SMEM_CTRL 1024
#define SMEM_TOTAL (SMEM_CTRL + STAGES * STAGE_BYTES) // 197632
#define NTHREADS 320                 // 8 compute warps + 2 producer warps

// ---------------- scratch: tf32-rounded, fragment-native layouts ----------------
// g_A: [b(128)][kc(256)][mtile(8)][t(32)*4 + j]   (4 KB per (b,kc))
// g_W: [nb(64)][kc(256)][ntile(32)][t(32)*2 + j]  (8 KB per (nb,kc))
__device__ float g_A[(size_t)NT * NIN];
__device__ float g_W[(size_t)NE * NOUT * NIN];

// ---------------- helpers (all plain-sm_103-legal) ----------------
__device__ __forceinline__ uint32_t smem_u32(const void* p) {
    uint32_t a;
    asm("{ .reg .u64 t; cvta.to.shared.u64 t, %1; cvt.u32.u64 %0, t; }" : "=r"(a) : "l"(p));
    return a;
}

__device__ __forceinline__ float tf32r(float f) {   // round-to-nearest tf32 (unbiased)
    uint32_t r;
    asm("cvt.rna.tf32.f32 %0, %1;" : "=r"(r) : "f"(f));
    return __uint_as_float(r);
}

__device__ __forceinline__ void cp16(uint32_t smem_dst, const float* gsrc) {
    asm volatile("cp.async.cg.shared.global [%0], [%1], 16;" :: "r"(smem_dst), "l"(gsrc));
}

#define MBAR_INIT(a, c) \
    asm volatile("mbarrier.init.shared.b64 [%0], %1;" :: "r"(a), "r"(c) : "memory")
#define MBAR_ARRIVE(a) \
    asm volatile("mbarrier.arrive.shared.b64 _, [%0];" :: "r"(a) : "memory")
// signal mbarrier when all of this thread's prior cp.asyncs have landed
#define CP_MBAR_ARRIVE(a) \
    asm volatile("cp.async.mbarrier.arrive.noinc.shared.b64 [%0];" :: "r"(a) : "memory")

#define MBAR_WAIT(addr, ph) do {                                                   \
    asm volatile("{\n\t.reg .pred P1;\n\t"                                         \
        "WL%=:\n\t"                                                                \
        "mbarrier.try_wait.parity.acquire.cta.shared::cta.b64 P1, [%0], %1, 0x989680;\n\t" \
        "@P1 bra.uni WD%=;\n\t"                                                    \
        "bra.uni WL%=;\n\t"                                                        \
        "WD%=:\n\t}"                                                               \
        :: "r"(addr), "r"(ph) : "memory");                                         \
} while (0)

__device__ __forceinline__ void lds128(uint32_t* r, uint32_t addr) {
    asm volatile("ld.shared.v4.b32 {%0,%1,%2,%3}, [%4];"
                 : "=r"(r[0]), "=r"(r[1]), "=r"(r[2]), "=r"(r[3]) : "r"(addr));
}
__device__ __forceinline__ void lds64(uint32_t* r, uint32_t addr) {
    asm volatile("ld.shared.v2.b32 {%0,%1}, [%2];"
                 : "=r"(r[0]), "=r"(r[1]) : "r"(addr));
}

__device__ __forceinline__ void mma_tf32(float* d, const uint32_t* a, const uint32_t* b) {
    asm volatile(
        "mma.sync.aligned.m16n8k8.row.col.f32.tf32.tf32.f32 "
        "{%0,%1,%2,%3}, {%4,%5,%6,%7}, {%8,%9}, {%0,%1,%2,%3};"
        : "+f"(d[0]), "+f"(d[1]), "+f"(d[2]), "+f"(d[3])
        : "r"(a[0]), "r"(a[1]), "r"(a[2]), "r"(a[3]), "r"(b[0]), "r"(b[1]));
}

// ---------------- pre-pass A: x[row][col] -> g_A fragment-native, tf32-rounded ----
__global__ void __launch_bounds__(256) prepA(const float* __restrict__ x) {
    uint32_t gid = blockIdx.x * 256 + threadIdx.x;     // [0, 2^21)
    int lrg   = gid & 7;
    int mtile = (gid >> 3) & 7;
    int kc    = (gid >> 6) & 255;
    int b     = gid >> 14;
    int row0  = b * 128 + mtile * 16 + lrg;
    int c     = kc * 8;

    const float* r0 = x + (size_t)row0 * NIN + c;
    const float* r1 = r0 + (size_t)8 * NIN;
    float4 u0 = *(const float4*)(r0);
    float4 u1 = *(const float4*)(r0 + 4);
    float4 v0 = *(const float4*)(r1);
    float4 v1 = *(const float4*)(r1 + 4);

    float* dst = g_A + ((((size_t)b * 256 + kc) * 8 + mtile) * 128) + lrg * 16;
    float4 o;
    o.x = tf32r(u0.x); o.y = tf32r(v0.x); o.z = tf32r(u1.x); o.w = tf32r(v1.x);
    *(float4*)(dst + 0)  = o;
    o.x = tf32r(u0.y); o.y = tf32r(v0.y); o.z = tf32r(u1.y); o.w = tf32r(v1.y);
    *(float4*)(dst + 4)  = o;
    o.x = tf32r(u0.z); o.y = tf32r(v0.z); o.z = tf32r(u1.z); o.w = tf32r(v1.z);
    *(float4*)(dst + 8)  = o;
    o.x = tf32r(u0.w); o.y = tf32r(v0.w); o.z = tf32r(u1.w); o.w = tf32r(v1.w);
    *(float4*)(dst + 12) = o;
}

// ---------------- pre-pass W: w[grow][col] -> g_W fragment-native ----------------
__global__ void __launch_bounds__(256) prepW(const float* __restrict__ w) {
    uint32_t gid = blockIdx.x * 256 + threadIdx.x;     // [0, 2^22)
    int ln    = gid & 7;
    int ntile = (gid >> 3) & 31;
    int kc    = (gid >> 8) & 255;
    int nb    = gid >> 16;
    int grow  = nb * 256 + ntile * 8 + ln;
    int c     = kc * 8;

    const float* r = w + (size_t)grow * NIN + c;
    float4 v0 = *(const float4*)(r);
    float4 v1 = *(const float4*)(r + 4);

    float* dst = g_W + ((((size_t)nb * 256 + kc) * 32 + ntile) * 64) + ln * 8;
    float4 o;
    o.x = tf32r(v0.x); o.y = tf32r(v1.x); o.z = tf32r(v0.y); o.w = tf32r(v1.y);
    *(float4*)(dst + 0) = o;
    o.x = tf32r(v0.z); o.y = tf32r(v1.z); o.z = tf32r(v0.w); o.w = tf32r(v1.w);
    *(float4*)(dst + 4) = o;
}

// ---------------- main grouped GEMM: warp-specialized mbarrier pipeline ---------
__global__ void __launch_bounds__(NTHREADS, 1) gemm_kernel(
        const float* __restrict__ bias,
        const int*   __restrict__ tpe,
        float*       __restrict__ out) {
    extern __shared__ __align__(16) char smem[];

    const int e  = blockIdx.z;
    const int mt = blockIdx.y;
    const int nt = blockIdx.x;

    int start = 0, mycnt = 0;
    #pragma unroll
    for (int i = 0; i < NE; i++) {
        int cc = __ldg(tpe + i);
        if (i < e) start += cc;
        if (i == e) mycnt = cc;
    }
    if (mt * BM >= mycnt) return;

    const int tid  = threadIdx.x;
    const int b    = (start >> 7) + mt;
    const int nb   = e * 8 + nt;
    const int m0   = start + mt * BM;

    const uint32_t sb     = smem_u32(smem);
    const uint32_t fullb  = sb;              // STAGES x 8B
    const uint32_t emptyb = sb + 64;         // STAGES x 8B
    const uint32_t dbase  = sb + SMEM_CTRL;

    const float* Ab = g_A + (size_t)b  * 256 * 1024;   // 16KB per k-iter, contiguous
    const float* Bb = g_W + (size_t)nb * 256 * 2048;   // 32KB per k-iter, contiguous

    if (tid == 0) {
        #pragma unroll
        for (int s = 0; s < STAGES; s++) {
            MBAR_INIT(fullb + s * 8, 64);     // 64 producer threads signal
            MBAR_INIT(emptyb + s * 8, 256);   // 256 compute threads signal
        }
    }
    __syncthreads();

    if (tid >= 256) {
        // ================= producer warps (2 warps, 64 threads) =================
        const int ptid = tid - 256;           // 0..63
        #pragma unroll 1
        for (int k = 0; k < KITERS; k++) {
            const int s = k & (STAGES - 1);
            if (k >= STAGES) MBAR_WAIT(emptyb + s * 8, ((k >> 2) - 1) & 1);
            const float* As = Ab + (size_t)k * 4096;
            const float* Bs = Bb + (size_t)k * 8192;
            const uint32_t dA = dbase + s * STAGE_BYTES;
            const uint32_t dB = dA + A_STAGE_BYTES;
            #pragma unroll
            for (int i = 0; i < 16; i++)      // A: 1024 x 16B chunks / 64 threads
                cp16(dA + (ptid + i * 64) * 16, As + (ptid + i * 64) * 4);
            #pragma unroll
            for (int i = 0; i < 32; i++)      // B: 2048 x 16B chunks / 64 threads
                cp16(dB + (ptid + i * 64) * 16, Bs + (ptid + i * 64) * 4);
            CP_MBAR_ARRIVE(fullb + s * 8);
        }
    } else {
        // ================= compute warps (8 warps, 256 threads) =================
        const int lane = tid & 31;
        const int wid  = tid >> 5;
        const int wm   = wid & 1;             // 2 warp rows (64 rows each)
        const int wn   = wid >> 1;            // 4 warp cols (64 cols each)

        float acc[4][8][4];
        #pragma unroll
        for (int i = 0; i < 4; i++)
            #pragma unroll
            for (int j = 0; j < 8; j++)
                #pragma unroll
                for (int k = 0; k < 4; k++) acc[i][j][k] = 0.0f;

        #pragma unroll 1
        for (int k = 0; k < KITERS; k++) {
            const int s = k & (STAGES - 1);
            MBAR_WAIT(fullb + s * 8, (k >> 2) & 1);
            const uint32_t aBase = dbase + s * STAGE_BYTES;
            const uint32_t bBase = aBase + A_STAGE_BYTES;
            #pragma unroll
            for (int kcl = 0; kcl < 4; kcl++) {
                uint32_t af[4][4], bf[8][2];
                #pragma unroll
                for (int i = 0; i < 4; i++)
                    lds128(af[i], aBase + ((kcl * 8 + wm * 4 + i) * 128 + lane * 4) * 4);
                #pragma unroll
                for (int j = 0; j < 8; j++)
                    lds64(bf[j], bBase + ((kcl * 32 + wn * 8 + j) * 64 + lane * 2) * 4);
                #pragma unroll
                for (int i = 0; i < 4; i++)
                    #pragma unroll
                    for (int j = 0; j < 8; j++)
                        mma_tf32(acc[i][j], af[i], bf[j]);
            }
            MBAR_ARRIVE(emptyb + s * 8);      // release: orders prior LDS reads
        }

        // ---- epilogue: bias add + fp32 store ----
        const int ncol0 = nt * BN + wn * 64;
        const float* bptr = bias + (size_t)e * NOUT + ncol0;
        #pragma unroll
        for (int j = 0; j < 8; j++) {
            const int cb = j * 8 + (lane & 3) * 2;
            const float bx = __ldg(bptr + cb);
            const float by = __ldg(bptr + cb + 1);
            #pragma unroll
            for (int i = 0; i < 4; i++) {
                const int r0 = wm * 64 + i * 16 + (lane >> 2);
                if (mt * BM + r0 < mycnt) {
                    float2 v = make_float2(acc[i][j][0] + bx, acc[i][j][1] + by);
                    *(float2*)(out + (size_t)(m0 + r0) * NOUT + ncol0 + cb) = v;
                }
                if (mt * BM + r0 + 8 < mycnt) {
                    float2 v = make_float2(acc[i][j][2] + bx, acc[i][j][3] + by);
                    *(float2*)(out + (size_t)(m0 + r0 + 8) * NOUT + ncol0 + cb) = v;
                }
            }
        }
    }
}

// ---------------- host launch ----------------
extern "C" void kernel_launch(void* const* d_in, const int* in_sizes, int n_in,
                              void* d_out, int out_size) {
    const float* x    = (const float*)d_in[0];
    const float* w    = (const float*)d_in[1];
    const float* bias = (const float*)d_in[2];
    const int*   tpe  = (const int*)d_in[3];
    float*       out  = (float*)d_out;

    prepA<<<8192, 256>>>(x);                               // 2^21 threads
    prepW<<<16384, 256>>>(w);                              // 2^22 threads

    cudaFuncSetAttribute(gemm_kernel,
                         cudaFuncAttributeMaxDynamicSharedMemorySize, SMEM_TOTAL);
    dim3 grid(NOUT / BN, NT / BM, NE);                     // (8, 128, 8), ragged exit
    gemm_kernel<<<grid, NTHREADS, SMEM_TOTAL>>>(bias, tpe, out);
}